// round 10
// baseline (speedup 1.0000x reference)
#include <cuda_runtime.h>
#include <math.h>

#define BATCH 2048
#define XF    1024
#define XF4   (XF / 4)
#define G     16

#define CH    64                // row chunks (32 rows each)
#define RPCH  (BATCH / CH)      // 32
#define RPT   4                 // rows per thread (8 subgroups x 4 rows)

// Scratch (allocation-free: __device__ globals)
__device__ float g_p0[CH * XF];
__device__ float g_p1[CH * XF];
__device__ float g_p2[CH * XF];
__device__ float g_mean[XF];

// ---------------------------------------------------------------------------
// K1: partial column sums. grid=(8,64): bx = 128-col group, by = 32-row chunk.
__global__ __launch_bounds__(256) void k1_sum(const float* __restrict__ xf) {
    __shared__ float4 sh[8][32];
    int c4 = threadIdx.x & 31, rg = threadIdx.x >> 5;
    int col4 = blockIdx.x * 32 + c4;
    int row0 = blockIdx.y * RPCH + rg * RPT;

    const float4* p = (const float4*)xf + (size_t)row0 * XF4 + col4;
    float4 s = make_float4(0.f, 0.f, 0.f, 0.f);
#pragma unroll
    for (int r = 0; r < RPT; r++) {
        float4 x = p[(size_t)r * XF4];
        s.x += x.x; s.y += x.y; s.z += x.z; s.w += x.w;
    }
    sh[rg][c4] = s;
    __syncthreads();
    if (rg == 0) {
        float4 t = sh[0][c4];
#pragma unroll
        for (int i = 1; i < 8; i++) {
            float4 u = sh[i][c4];
            t.x += u.x; t.y += u.y; t.z += u.z; t.w += u.w;
        }
        ((float4*)(g_p0 + blockIdx.y * XF))[col4] = t;
    }
}

// ---------------------------------------------------------------------------
// K2: prologue folds the 64 mean-partials in-block, then stats partials.
__global__ __launch_bounds__(256) void k2_stats(const float* __restrict__ xf) {
    __shared__ float4 sh[8][32];
    __shared__ float4 shm[32];
    int c4 = threadIdx.x & 31, rg = threadIdx.x >> 5;
    int col4 = blockIdx.x * 32 + c4;
    int row0 = blockIdx.y * RPCH + rg * RPT;

    // mean fold: subgroup rg folds chunks [rg*8, rg*8+8)
    {
        float4 s = make_float4(0.f, 0.f, 0.f, 0.f);
#pragma unroll
        for (int i = 0; i < 8; i++) {
            float4 u = ((const float4*)(g_p0 + (rg * 8 + i) * XF))[col4];
            s.x += u.x; s.y += u.y; s.z += u.z; s.w += u.w;
        }
        sh[rg][c4] = s;
    }
    __syncthreads();
    if (rg == 0) {
        float4 t = sh[0][c4];
#pragma unroll
        for (int i = 1; i < 8; i++) {
            float4 u = sh[i][c4];
            t.x += u.x; t.y += u.y; t.z += u.z; t.w += u.w;
        }
        const float inv = 1.0f / BATCH;
        t.x *= inv; t.y *= inv; t.z *= inv; t.w *= inv;
        shm[c4] = t;
        if (blockIdx.y == 0) ((float4*)g_mean)[col4] = t;
    }
    __syncthreads();
    float4 m = shm[c4];

    const float4* p = (const float4*)xf + (size_t)row0 * XF4 + col4;
    float4 s1 = make_float4(0.f, 0.f, 0.f, 0.f);
    float4 s2 = make_float4(0.f, 0.f, 0.f, 0.f);
#pragma unroll
    for (int r = 0; r < RPT; r++) {
        float4 x = p[(size_t)r * XF4];
        float vx = fmaxf(x.x - m.x, 0.f);
        float vy = fmaxf(x.y - m.y, 0.f);
        float vz = fmaxf(x.z - m.z, 0.f);
        float vw = fmaxf(x.w - m.w, 0.f);
        s1.x += vx; s1.y += vy; s1.z += vz; s1.w += vw;
        s2.x += vx * vx; s2.y += vy * vy; s2.z += vz * vz; s2.w += vw * vw;
    }
    __syncthreads();
    sh[rg][c4] = s1;
    __syncthreads();
    if (rg == 0) {
        float4 t = sh[0][c4];
#pragma unroll
        for (int i = 1; i < 8; i++) {
            float4 u = sh[i][c4];
            t.x += u.x; t.y += u.y; t.z += u.z; t.w += u.w;
        }
        ((float4*)(g_p1 + blockIdx.y * XF))[col4] = t;
    }
    __syncthreads();
    sh[rg][c4] = s2;
    __syncthreads();
    if (rg == 0) {
        float4 t = sh[0][c4];
#pragma unroll
        for (int i = 1; i < 8; i++) {
            float4 u = sh[i][c4];
            t.x += u.x; t.y += u.y; t.z += u.z; t.w += u.w;
        }
        ((float4*)(g_p2 + blockIdx.y * XF))[col4] = t;
    }
}

// ---------------------------------------------------------------------------
// K3: fold stats partials for this 64-col tile -> (a,b), then write 16-way
// tiled output. grid=(16,32): bx = 64-col tile, by = 64-row tile. block=256.
// Normal stores (no .cs): land in L2, writeback overlaps across replays.
#define COLS_B 64
#define ROWS_B 64
__global__ __launch_bounds__(256) void k3_out(const float* __restrict__ xf,
                                              const float* __restrict__ wp,
                                              float* __restrict__ out) {
    __shared__ float sh1[4][COLS_B], sh2[4][COLS_B];
    __shared__ float s_m[COLS_B], s_a[COLS_B], s_b[COLS_B];
    int tid = threadIdx.x;
    int col0 = blockIdx.x * COLS_B;

    {   // fold: cc = col, gg folds 16 chunks each
        int cc = tid & 63, gg = tid >> 6;
        int col = col0 + cc;
        float s1 = 0.f, s2 = 0.f;
#pragma unroll
        for (int i = 0; i < 16; i++) {
            int idx = (gg * 16 + i) * XF + col;
            s1 += g_p1[idx];
            s2 += g_p2[idx];
        }
        sh1[gg][cc] = s1;
        sh2[gg][cc] = s2;
    }
    __syncthreads();
    if (tid < COLS_B) {
        float s1 = sh1[0][tid] + sh1[1][tid] + sh1[2][tid] + sh1[3][tid];
        float s2 = sh2[0][tid] + sh2[1][tid] + sh2[2][tid] + sh2[3][tid];
        float mu  = s1 * (1.0f / BATCH);
        float var = (s2 - (float)BATCH * mu * mu) * (1.0f / (BATCH - 1));
        float a   = wp[0] * rsqrtf(var);
        s_m[tid] = g_mean[col0 + tid];
        s_a[tid] = a;
        s_b[tid] = -a * mu;
    }
    __syncthreads();

    int cidx = tid & 15;          // float4 within the 64-col tile
    int ridx = tid >> 4;          // 0..15
    int col  = col0 + cidx * 4;

    float4 m = *(const float4*)(s_m + cidx * 4);
    float4 a = *(const float4*)(s_a + cidx * 4);
    float4 b = *(const float4*)(s_b + cidx * 4);

#pragma unroll
    for (int j = 0; j < ROWS_B / 16; j++) {     // 4 rows per thread
        int row = blockIdx.y * ROWS_B + ridx + j * 16;
        float4 x = *(const float4*)(xf + (size_t)row * XF + col);
        float4 v;
        v.x = fmaxf(x.x - m.x, 0.f) * a.x + b.x;
        v.y = fmaxf(x.y - m.y, 0.f) * a.y + b.y;
        v.z = fmaxf(x.z - m.z, 0.f) * a.z + b.z;
        v.w = fmaxf(x.w - m.w, 0.f) * a.w + b.w;

        float* orow = out + (size_t)row * (G * XF) + col;
#pragma unroll
        for (int k = 0; k < G; k++)
            *(float4*)(orow + (size_t)k * XF) = v;
    }
}

extern "C" void kernel_launch(void* const* d_in, const int* in_sizes, int n_in,
                              void* d_out, int out_size) {
    const float* xf = (const float*)d_in[0];
    const float* wp = (const float*)d_in[1];
    float* out = (float*)d_out;

    k1_sum<<<dim3(8, CH), 256>>>(xf);
    k2_stats<<<dim3(8, CH), 256>>>(xf);
    k3_out<<<dim3(XF / COLS_B, BATCH / ROWS_B), 256>>>(xf, wp, out);
}

// round 11
// speedup vs baseline: 1.0626x; 1.0626x over previous
#include <cuda_runtime.h>
#include <math.h>

#define BATCH 2048
#define XF    1024
#define XF4   (XF / 4)
#define G     16

#define CH    64                // row chunks (32 rows each)
#define RPCH  (BATCH / CH)      // 32
#define RPT   4                 // rows per thread (8 subgroups x 4 rows)

// Scratch (allocation-free: __device__ globals)
__device__ float g_p0[CH * XF];
__device__ float g_p1[CH * XF];
__device__ float g_p2[CH * XF];
__device__ float g_mean[XF];

// ---------------------------------------------------------------------------
// K1: partial column sums. grid=(8,64): bx = 128-col group, by = 32-row chunk.
__global__ __launch_bounds__(256) void k1_sum(const float* __restrict__ xf) {
    __shared__ float4 sh[8][32];
    int c4 = threadIdx.x & 31, rg = threadIdx.x >> 5;
    int col4 = blockIdx.x * 32 + c4;
    int row0 = blockIdx.y * RPCH + rg * RPT;

    const float4* p = (const float4*)xf + (size_t)row0 * XF4 + col4;
    float4 s = make_float4(0.f, 0.f, 0.f, 0.f);
#pragma unroll
    for (int r = 0; r < RPT; r++) {
        float4 x = p[(size_t)r * XF4];
        s.x += x.x; s.y += x.y; s.z += x.z; s.w += x.w;
    }
    sh[rg][c4] = s;
    __syncthreads();
    if (rg == 0) {
        float4 t = sh[0][c4];
#pragma unroll
        for (int i = 1; i < 8; i++) {
            float4 u = sh[i][c4];
            t.x += u.x; t.y += u.y; t.z += u.z; t.w += u.w;
        }
        ((float4*)(g_p0 + blockIdx.y * XF))[col4] = t;
    }
}

// ---------------------------------------------------------------------------
// K2: prologue folds the 64 mean-partials in-block, then stats partials.
__global__ __launch_bounds__(256) void k2_stats(const float* __restrict__ xf) {
    __shared__ float4 sh[8][32];
    __shared__ float4 shm[32];
    int c4 = threadIdx.x & 31, rg = threadIdx.x >> 5;
    int col4 = blockIdx.x * 32 + c4;
    int row0 = blockIdx.y * RPCH + rg * RPT;

    // mean fold: subgroup rg folds chunks [rg*8, rg*8+8)
    {
        float4 s = make_float4(0.f, 0.f, 0.f, 0.f);
#pragma unroll
        for (int i = 0; i < 8; i++) {
            float4 u = ((const float4*)(g_p0 + (rg * 8 + i) * XF))[col4];
            s.x += u.x; s.y += u.y; s.z += u.z; s.w += u.w;
        }
        sh[rg][c4] = s;
    }
    __syncthreads();
    if (rg == 0) {
        float4 t = sh[0][c4];
#pragma unroll
        for (int i = 1; i < 8; i++) {
            float4 u = sh[i][c4];
            t.x += u.x; t.y += u.y; t.z += u.z; t.w += u.w;
        }
        const float inv = 1.0f / BATCH;
        t.x *= inv; t.y *= inv; t.z *= inv; t.w *= inv;
        shm[c4] = t;
        if (blockIdx.y == 0) ((float4*)g_mean)[col4] = t;
    }
    __syncthreads();
    float4 m = shm[c4];

    const float4* p = (const float4*)xf + (size_t)row0 * XF4 + col4;
    float4 s1 = make_float4(0.f, 0.f, 0.f, 0.f);
    float4 s2 = make_float4(0.f, 0.f, 0.f, 0.f);
#pragma unroll
    for (int r = 0; r < RPT; r++) {
        float4 x = p[(size_t)r * XF4];
        float vx = fmaxf(x.x - m.x, 0.f);
        float vy = fmaxf(x.y - m.y, 0.f);
        float vz = fmaxf(x.z - m.z, 0.f);
        float vw = fmaxf(x.w - m.w, 0.f);
        s1.x += vx; s1.y += vy; s1.z += vz; s1.w += vw;
        s2.x += vx * vx; s2.y += vy * vy; s2.z += vz * vz; s2.w += vw * vw;
    }
    __syncthreads();
    sh[rg][c4] = s1;
    __syncthreads();
    if (rg == 0) {
        float4 t = sh[0][c4];
#pragma unroll
        for (int i = 1; i < 8; i++) {
            float4 u = sh[i][c4];
            t.x += u.x; t.y += u.y; t.z += u.z; t.w += u.w;
        }
        ((float4*)(g_p1 + blockIdx.y * XF))[col4] = t;
    }
    __syncthreads();
    sh[rg][c4] = s2;
    __syncthreads();
    if (rg == 0) {
        float4 t = sh[0][c4];
#pragma unroll
        for (int i = 1; i < 8; i++) {
            float4 u = sh[i][c4];
            t.x += u.x; t.y += u.y; t.z += u.z; t.w += u.w;
        }
        ((float4*)(g_p2 + blockIdx.y * XF))[col4] = t;
    }
}

// ---------------------------------------------------------------------------
// K3: fold stats partials for this 64-col tile -> (a,b); write 16-way tiled
// output with STREAMING stores. grid=(16,32): bx = 64-col tile, by = 64-row
// tile (512 blocks -> ~4 blocks/SM during the store phase). block=256.
#define COLS_B 64
#define ROWS_B 64
__global__ __launch_bounds__(256) void k3_out(const float* __restrict__ xf,
                                              const float* __restrict__ wp,
                                              float* __restrict__ out) {
    __shared__ float sh1[4][COLS_B], sh2[4][COLS_B];
    __shared__ float s_m[COLS_B], s_a[COLS_B], s_b[COLS_B];
    int tid = threadIdx.x;
    int col0 = blockIdx.x * COLS_B;

    {   // fold: cc = col, gg folds 16 chunks each
        int cc = tid & 63, gg = tid >> 6;
        int col = col0 + cc;
        float s1 = 0.f, s2 = 0.f;
#pragma unroll
        for (int i = 0; i < 16; i++) {
            int idx = (gg * 16 + i) * XF + col;
            s1 += g_p1[idx];
            s2 += g_p2[idx];
        }
        sh1[gg][cc] = s1;
        sh2[gg][cc] = s2;
    }
    __syncthreads();
    if (tid < COLS_B) {
        float s1 = sh1[0][tid] + sh1[1][tid] + sh1[2][tid] + sh1[3][tid];
        float s2 = sh2[0][tid] + sh2[1][tid] + sh2[2][tid] + sh2[3][tid];
        float mu  = s1 * (1.0f / BATCH);
        float var = (s2 - (float)BATCH * mu * mu) * (1.0f / (BATCH - 1));
        float a   = wp[0] * rsqrtf(var);
        s_m[tid] = g_mean[col0 + tid];
        s_a[tid] = a;
        s_b[tid] = -a * mu;
    }
    __syncthreads();

    int cidx = tid & 15;          // float4 within the 64-col tile
    int ridx = tid >> 4;          // 0..15
    int col  = col0 + cidx * 4;

    float4 m = *(const float4*)(s_m + cidx * 4);
    float4 a = *(const float4*)(s_a + cidx * 4);
    float4 b = *(const float4*)(s_b + cidx * 4);

#pragma unroll
    for (int j = 0; j < ROWS_B / 16; j++) {     // 4 rows per thread
        int row = blockIdx.y * ROWS_B + ridx + j * 16;
        float4 x = *(const float4*)(xf + (size_t)row * XF + col);
        float4 v;
        v.x = fmaxf(x.x - m.x, 0.f) * a.x + b.x;
        v.y = fmaxf(x.y - m.y, 0.f) * a.y + b.y;
        v.z = fmaxf(x.z - m.z, 0.f) * a.z + b.z;
        v.w = fmaxf(x.w - m.w, 0.f) * a.w + b.w;

        float* orow = out + (size_t)row * (G * XF) + col;
#pragma unroll
        for (int k = 0; k < G; k++)
            __stcs((float4*)(orow + (size_t)k * XF), v);
    }
}

extern "C" void kernel_launch(void* const* d_in, const int* in_sizes, int n_in,
                              void* d_out, int out_size) {
    const float* xf = (const float*)d_in[0];
    const float* wp = (const float*)d_in[1];
    float* out = (float*)d_out;

    k1_sum<<<dim3(8, CH), 256>>>(xf);
    k2_stats<<<dim3(8, CH), 256>>>(xf);
    k3_out<<<dim3(XF / COLS_B, BATCH / ROWS_B), 256>>>(xf, wp, out);
}

// round 12
// speedup vs baseline: 1.1323x; 1.0656x over previous
#include <cuda_runtime.h>
#include <math.h>

#define BATCH 2048
#define XF    1024
#define XF4   (XF / 4)
#define G     16

#define CH    32                // row chunks (64 rows each)
#define RPCH  (BATCH / CH)      // 64 rows per chunk
#define RPT   8                 // rows per thread inside a chunk

// Scratch (allocation-free: __device__ globals)
__device__ float g_p0[CH * XF];     // per-chunk column sums of xf
__device__ float g_p1[CH * XF];     // per-chunk sums of relu(x-mean)
__device__ float g_p2[CH * XF];     // per-chunk sums of squares
__device__ float g_mean[XF];

// ---------------------------------------------------------------------------
// K1: partial column sums. grid=(8,32): bx = 128-col group, by = 64-row chunk.
// (R7-identical.)
__global__ __launch_bounds__(256) void k1_sum(const float* __restrict__ xf) {
    __shared__ float4 sh[8][32];
    int c4 = threadIdx.x & 31, rg = threadIdx.x >> 5;
    int col4 = blockIdx.x * 32 + c4;
    int row0 = blockIdx.y * RPCH + rg * RPT;

    const float4* p = (const float4*)xf + (size_t)row0 * XF4 + col4;
    float4 s = make_float4(0.f, 0.f, 0.f, 0.f);
#pragma unroll
    for (int r = 0; r < RPT; r++) {
        float4 x = p[(size_t)r * XF4];
        s.x += x.x; s.y += x.y; s.z += x.z; s.w += x.w;
    }
    sh[rg][c4] = s;
    __syncthreads();
    if (rg == 0) {
        float4 t = sh[0][c4];
#pragma unroll
        for (int i = 1; i < 8; i++) {
            float4 u = sh[i][c4];
            t.x += u.x; t.y += u.y; t.z += u.z; t.w += u.w;
        }
        ((float4*)(g_p0 + blockIdx.y * XF))[col4] = t;
    }
}

// ---------------------------------------------------------------------------
// K2: prologue folds the 32 mean-partials in-block, then stats partials.
// (R7-identical.)
__global__ __launch_bounds__(256) void k2_stats(const float* __restrict__ xf) {
    __shared__ float4 sh[8][32];
    __shared__ float4 shm[32];
    int c4 = threadIdx.x & 31, rg = threadIdx.x >> 5;
    int col4 = blockIdx.x * 32 + c4;
    int row0 = blockIdx.y * RPCH + rg * RPT;

    // mean fold: subgroup rg folds chunks [rg*4, rg*4+4)
    {
        float4 s = make_float4(0.f, 0.f, 0.f, 0.f);
#pragma unroll
        for (int i = 0; i < 4; i++) {
            float4 u = ((const float4*)(g_p0 + (rg * 4 + i) * XF))[col4];
            s.x += u.x; s.y += u.y; s.z += u.z; s.w += u.w;
        }
        sh[rg][c4] = s;
    }
    __syncthreads();
    if (rg == 0) {
        float4 t = sh[0][c4];
#pragma unroll
        for (int i = 1; i < 8; i++) {
            float4 u = sh[i][c4];
            t.x += u.x; t.y += u.y; t.z += u.z; t.w += u.w;
        }
        const float inv = 1.0f / BATCH;
        t.x *= inv; t.y *= inv; t.z *= inv; t.w *= inv;
        shm[c4] = t;
        if (blockIdx.y == 0) ((float4*)g_mean)[col4] = t;
    }
    __syncthreads();
    float4 m = shm[c4];

    const float4* p = (const float4*)xf + (size_t)row0 * XF4 + col4;
    float4 s1 = make_float4(0.f, 0.f, 0.f, 0.f);
    float4 s2 = make_float4(0.f, 0.f, 0.f, 0.f);
#pragma unroll
    for (int r = 0; r < RPT; r++) {
        float4 x = p[(size_t)r * XF4];
        float vx = fmaxf(x.x - m.x, 0.f);
        float vy = fmaxf(x.y - m.y, 0.f);
        float vz = fmaxf(x.z - m.z, 0.f);
        float vw = fmaxf(x.w - m.w, 0.f);
        s1.x += vx; s1.y += vy; s1.z += vz; s1.w += vw;
        s2.x += vx * vx; s2.y += vy * vy; s2.z += vz * vz; s2.w += vw * vw;
    }
    __syncthreads();
    sh[rg][c4] = s1;
    __syncthreads();
    if (rg == 0) {
        float4 t = sh[0][c4];
#pragma unroll
        for (int i = 1; i < 8; i++) {
            float4 u = sh[i][c4];
            t.x += u.x; t.y += u.y; t.z += u.z; t.w += u.w;
        }
        ((float4*)(g_p1 + blockIdx.y * XF))[col4] = t;
    }
    __syncthreads();
    sh[rg][c4] = s2;
    __syncthreads();
    if (rg == 0) {
        float4 t = sh[0][c4];
#pragma unroll
        for (int i = 1; i < 8; i++) {
            float4 u = sh[i][c4];
            t.x += u.x; t.y += u.y; t.z += u.z; t.w += u.w;
        }
        ((float4*)(g_p2 + blockIdx.y * XF))[col4] = t;
    }
}

// ---------------------------------------------------------------------------
// K3: fold stats partials for this 64-col tile -> (a,b); write 16-way tiled
// output with streaming stores. grid=(16,16) (R7 shape) but 512 threads:
// doubles resident warps per SM without changing fold traffic or tiles.
#define COLS_B 64
#define ROWS_B 128
__global__ __launch_bounds__(512) void k3_out(const float* __restrict__ xf,
                                              const float* __restrict__ wp,
                                              float* __restrict__ out) {
    __shared__ float sh1[8][COLS_B], sh2[8][COLS_B];
    __shared__ float s_m[COLS_B], s_a[COLS_B], s_b[COLS_B];
    int tid = threadIdx.x;
    int col0 = blockIdx.x * COLS_B;

    {   // fold: cc = col, gg folds 4 chunks each (8 groups x 4 = 32 chunks)
        int cc = tid & 63, gg = tid >> 6;
        int col = col0 + cc;
        float s1 = 0.f, s2 = 0.f;
#pragma unroll
        for (int i = 0; i < 4; i++) {
            int idx = (gg * 4 + i) * XF + col;
            s1 += g_p1[idx];
            s2 += g_p2[idx];
        }
        sh1[gg][cc] = s1;
        sh2[gg][cc] = s2;
    }
    __syncthreads();
    if (tid < COLS_B) {
        float s1 = 0.f, s2 = 0.f;
#pragma unroll
        for (int i = 0; i < 8; i++) { s1 += sh1[i][tid]; s2 += sh2[i][tid]; }
        float mu  = s1 * (1.0f / BATCH);
        float var = (s2 - (float)BATCH * mu * mu) * (1.0f / (BATCH - 1));
        float a   = wp[0] * rsqrtf(var);
        s_m[tid] = g_mean[col0 + tid];
        s_a[tid] = a;
        s_b[tid] = -a * mu;
    }
    __syncthreads();

    int cidx = tid & 15;          // float4 within the 64-col tile
    int ridx = tid >> 4;          // 0..31
    int col  = col0 + cidx * 4;

    float4 m = *(const float4*)(s_m + cidx * 4);
    float4 a = *(const float4*)(s_a + cidx * 4);
    float4 b = *(const float4*)(s_b + cidx * 4);

#pragma unroll
    for (int j = 0; j < ROWS_B / 32; j++) {     // 4 rows per thread
        int row = blockIdx.y * ROWS_B + ridx + j * 32;
        float4 x = *(const float4*)(xf + (size_t)row * XF + col);
        float4 v;
        v.x = fmaxf(x.x - m.x, 0.f) * a.x + b.x;
        v.y = fmaxf(x.y - m.y, 0.f) * a.y + b.y;
        v.z = fmaxf(x.z - m.z, 0.f) * a.z + b.z;
        v.w = fmaxf(x.w - m.w, 0.f) * a.w + b.w;

        float* orow = out + (size_t)row * (G * XF) + col;
#pragma unroll
        for (int k = 0; k < G; k++)
            __stcs((float4*)(orow + (size_t)k * XF), v);
    }
}

extern "C" void kernel_launch(void* const* d_in, const int* in_sizes, int n_in,
                              void* d_out, int out_size) {
    const float* xf = (const float*)d_in[0];
    const float* wp = (const float*)d_in[1];
    float* out = (float*)d_out;

    k1_sum<<<dim3(8, CH), 256>>>(xf);
    k2_stats<<<dim3(8, CH), 256>>>(xf);
    k3_out<<<dim3(XF / COLS_B, BATCH / ROWS_B), 512>>>(xf, wp, out);
}